// round 1
// baseline (speedup 1.0000x reference)
#include <cuda_runtime.h>
#include <cuda_bf16.h>
#include <math.h>

// Problem constants
#define BATCH 4
#define SEQ   2048
#define DIM   1024
#define MPROJ (BATCH * SEQ)          // 8192

// ---------------------------------------------------------------------------
// Scratch (device globals — no allocation allowed in kernel_launch)
// ---------------------------------------------------------------------------
__device__ float g_q1[BATCH * SEQ * DIM];       // 32 MB
__device__ float g_k1[BATCH * SEQ * DIM];       // 32 MB
__device__ float g_v1[BATCH * SEQ * DIM];       // 32 MB
__device__ float g_sc[(long)BATCH * SEQ * SEQ]; // 64 MB  (scores / probs)

// ---------------------------------------------------------------------------
// SGEMM: C[M,N] = A[M,K] @ B  (B row-major [K,N] if !TRANSB, [N,K] if TRANSB)
// 128x128 block tile, BK=8, 8x8 per thread, register double buffering.
// CSKIP : skip blocks entirely above the causal diagonal (scores GEMM)
// CKLIM : limit K to m0+BM (P@V GEMM; P is zero beyond the diagonal)
// ---------------------------------------------------------------------------
#define BMg 128
#define BNg 128
#define BKg 8
#define TMg 8
#define TNg 8

template <bool TRANSB, bool CSKIP, bool CKLIM>
__global__ __launch_bounds__(256, 2) void sgemm_kernel(
    const float* __restrict__ A, const float* __restrict__ Bm,
    float* __restrict__ C, int M, int N, int K,
    long sA, long sB, long sC)
{
    const int m0 = blockIdx.y * BMg;
    const int n0 = blockIdx.x * BNg;
    if (CSKIP && n0 >= m0 + BMg) return;   // block fully masked

    A  += (long)blockIdx.z * sA;
    Bm += (long)blockIdx.z * sB;
    C  += (long)blockIdx.z * sC;

    const int kEnd = CKLIM ? ((m0 + BMg < K) ? (m0 + BMg) : K) : K;
    const int nT   = kEnd / BKg;

    __shared__ float As[2][BKg * BMg];  // stored transposed: As[k][m]
    __shared__ float Bs[2][BKg * BNg];  // Bs[k][n]

    const int tid = threadIdx.x;
    const int w = tid >> 5, l = tid & 31;
    // warp-tiled thread map: warp covers 4 rows x 8 cols of thread tiles
    const int trow = (w >> 1) * 4 + (l >> 3);   // 0..15
    const int tcol = (w & 1) * 8 + (l & 7);     // 0..15

    // A tile load: 128 rows x 8 k, one float4 per thread
    const int aRow = tid >> 1;
    const int aCol = (tid & 1) << 2;
    // B tile load
    int bRow, bCol;
    if (TRANSB) { bRow = tid >> 1; bCol = (tid & 1) << 2; }   // [n,k] layout
    else        { bRow = tid >> 5; bCol = (tid & 31) << 2; }  // [k,n] layout

    const float* Abase = A + (long)(m0 + aRow) * K + aCol;
    const float* Bbase = TRANSB ? (Bm + (long)(n0 + bRow) * K + bCol)
                                : (Bm + (long)bRow * N + n0 + bCol);

    float4 aR = *(const float4*)Abase;
    float4 bR = *(const float4*)Bbase;

    // store tile 0 into buffer 0
    As[0][(aCol + 0) * BMg + aRow] = aR.x;
    As[0][(aCol + 1) * BMg + aRow] = aR.y;
    As[0][(aCol + 2) * BMg + aRow] = aR.z;
    As[0][(aCol + 3) * BMg + aRow] = aR.w;
    if (TRANSB) {
        Bs[0][(bCol + 0) * BNg + bRow] = bR.x;
        Bs[0][(bCol + 1) * BNg + bRow] = bR.y;
        Bs[0][(bCol + 2) * BNg + bRow] = bR.z;
        Bs[0][(bCol + 3) * BNg + bRow] = bR.w;
    } else {
        *(float4*)&Bs[0][bRow * BNg + bCol] = bR;
    }
    __syncthreads();

    float acc[TMg][TNg] = {};

    for (int t = 0; t < nT; t++) {
        const int cur = t & 1;
        if (t + 1 < nT) {   // prefetch next tile into registers
            aR = *(const float4*)(Abase + (t + 1) * BKg);
            bR = TRANSB ? *(const float4*)(Bbase + (t + 1) * BKg)
                        : *(const float4*)(Bbase + (long)(t + 1) * BKg * N);
        }
#pragma unroll
        for (int k = 0; k < BKg; k++) {
            float a[TMg], b[TNg];
#pragma unroll
            for (int i = 0; i < TMg; i++) a[i] = As[cur][k * BMg + trow * TMg + i];
#pragma unroll
            for (int j = 0; j < TNg; j++) b[j] = Bs[cur][k * BNg + tcol * TNg + j];
#pragma unroll
            for (int i = 0; i < TMg; i++)
#pragma unroll
                for (int j = 0; j < TNg; j++)
                    acc[i][j] = fmaf(a[i], b[j], acc[i][j]);
        }
        if (t + 1 < nT) {
            const int nxt = cur ^ 1;
            As[nxt][(aCol + 0) * BMg + aRow] = aR.x;
            As[nxt][(aCol + 1) * BMg + aRow] = aR.y;
            As[nxt][(aCol + 2) * BMg + aRow] = aR.z;
            As[nxt][(aCol + 3) * BMg + aRow] = aR.w;
            if (TRANSB) {
                Bs[nxt][(bCol + 0) * BNg + bRow] = bR.x;
                Bs[nxt][(bCol + 1) * BNg + bRow] = bR.y;
                Bs[nxt][(bCol + 2) * BNg + bRow] = bR.z;
                Bs[nxt][(bCol + 3) * BNg + bRow] = bR.w;
            } else {
                *(float4*)&Bs[nxt][bRow * BNg + bCol] = bR;
            }
            __syncthreads();
        }
    }

    // epilogue
#pragma unroll
    for (int i = 0; i < TMg; i++) {
        const long row = m0 + trow * TMg + i;
#pragma unroll
        for (int j = 0; j < TNg; j += 4) {
            float4 v4 = make_float4(acc[i][j], acc[i][j + 1],
                                    acc[i][j + 2], acc[i][j + 3]);
            *(float4*)&C[row * N + n0 + tcol * TNg + j] = v4;
        }
    }
}

// ---------------------------------------------------------------------------
// Causal softmax over rows of g_sc, in place. One block per (batch,row).
// Writes exact zeros above the diagonal (so P@V can read the full row).
// ---------------------------------------------------------------------------
__device__ __forceinline__ float warpMax(float v) {
#pragma unroll
    for (int o = 16; o; o >>= 1) v = fmaxf(v, __shfl_xor_sync(0xffffffffu, v, o));
    return v;
}
__device__ __forceinline__ float warpSum(float v) {
#pragma unroll
    for (int o = 16; o; o >>= 1) v += __shfl_xor_sync(0xffffffffu, v, o);
    return v;
}

__global__ void softmax_causal_kernel(float* __restrict__ Smat)
{
    const int Sdim = SEQ;
    const long r = blockIdx.x;          // 0 .. BATCH*SEQ-1
    const int i = (int)(r % Sdim);      // row within batch (causal length i+1)
    float* row = Smat + r * (long)Sdim;
    const int n = i + 1;
    const int tid = threadIdx.x;
    const float scale = 0.03125f;       // rsqrt(1024)
    __shared__ float red[8];

    float m = -1e30f;
    for (int j = tid; j < n; j += 256) m = fmaxf(m, row[j] * scale);
    m = warpMax(m);
    if ((tid & 31) == 0) red[tid >> 5] = m;
    __syncthreads();
    if (tid < 32) {
        float v = (tid < 8) ? red[tid] : -1e30f;
        v = warpMax(v);
        if (tid == 0) red[0] = v;
    }
    __syncthreads();
    const float bm = red[0];
    __syncthreads();

    float s = 0.0f;
    for (int j = tid; j < n; j += 256) s += __expf(row[j] * scale - bm);
    s = warpSum(s);
    if ((tid & 31) == 0) red[tid >> 5] = s;
    __syncthreads();
    if (tid < 32) {
        float v = (tid < 8) ? red[tid] : 0.0f;
        v = warpSum(v);
        if (tid == 0) red[0] = v;
    }
    __syncthreads();
    const float inv = 1.0f / red[0];

    for (int j = tid; j < n; j += 256) row[j] = __expf(row[j] * scale - bm) * inv;
    for (int j = n + tid; j < Sdim; j += 256) row[j] = 0.0f;
}

// ---------------------------------------------------------------------------
// Launch
// ---------------------------------------------------------------------------
extern "C" void kernel_launch(void* const* d_in, const int* in_sizes, int n_in,
                              void* d_out, int out_size)
{
    // Defensive input mapping by element count:
    //   q,k,v : B*S*D = 8388608 ; mask : B*S*S = 16777216 ; W : D*D = 1048576
    const float* qkv[3] = {nullptr, nullptr, nullptr};
    const float* Ws[3]  = {nullptr, nullptr, nullptr};
    int nq = 0, nw = 0;
    for (int idx = 0; idx < n_in; idx++) {
        const long sz = in_sizes[idx];
        if (sz == (long)BATCH * SEQ * DIM && nq < 3)      qkv[nq++] = (const float*)d_in[idx];
        else if (sz == (long)DIM * DIM && nw < 3)         Ws[nw++]  = (const float*)d_in[idx];
        // mask (B*S*S bools) ignored — causal structure is known
    }
    const float* q = qkv[0];  const float* k = qkv[1];  const float* v = qkv[2];
    const float* Wq = Ws[0];  const float* Wk = Ws[1];  const float* Wv = Ws[2];
    float* out = (float*)d_out;

    float *q1, *k1, *v1, *sc;
    cudaGetSymbolAddress((void**)&q1, g_q1);
    cudaGetSymbolAddress((void**)&k1, g_k1);
    cudaGetSymbolAddress((void**)&v1, g_v1);
    cudaGetSymbolAddress((void**)&sc, g_sc);

    const dim3 blk(256);

    // 1) Projections: [8192,1024] @ [1024,1024]
    {
        dim3 grid(DIM / BNg, MPROJ / BMg, 1);
        sgemm_kernel<false, false, false><<<grid, blk>>>(q, Wq, q1, MPROJ, DIM, DIM, 0, 0, 0);
        sgemm_kernel<false, false, false><<<grid, blk>>>(k, Wk, k1, MPROJ, DIM, DIM, 0, 0, 0);
        sgemm_kernel<false, false, false><<<grid, blk>>>(v, Wv, v1, MPROJ, DIM, DIM, 0, 0, 0);
    }

    // 2) Scores: per batch, S = Q1 @ K1^T  (NT GEMM, causal block skip)
    {
        dim3 grid(SEQ / BNg, SEQ / BMg, BATCH);
        sgemm_kernel<true, true, false><<<grid, blk>>>(
            q1, k1, sc, SEQ, SEQ, DIM,
            (long)SEQ * DIM, (long)SEQ * DIM, (long)SEQ * SEQ);
    }

    // 3) Causal softmax in place (writes zeros above diagonal)
    softmax_causal_kernel<<<BATCH * SEQ, 256>>>(sc);

    // 4) Output: per batch, O = P @ V1  (NN GEMM, K limited to diagonal)
    {
        dim3 grid(DIM / BNg, SEQ / BMg, BATCH);
        sgemm_kernel<false, false, true><<<grid, blk>>>(
            sc, v1, out, SEQ, DIM, SEQ,
            (long)SEQ * SEQ, (long)SEQ * DIM, (long)SEQ * DIM);
    }
}